// round 9
// baseline (speedup 1.0000x reference)
#include <cuda_runtime.h>
#include <cstdint>

#define NN 100000
#define NE 1600000
#define DIN 128
#define DH 64
#define NG 512
#define NB 391              // ceil(NN/256)
#define GEMM_BLOCKS 782     // ceil(NN/128)
#define GEMM_A 391
#define GEMM_B (GEMM_BLOCKS - GEMM_A)   // 391
#define EDGE_BLOCKS 1563    // ceil(NE/(256*4))
#define EDGE_STRIDE (EDGE_BLOCKS * 256)

// ---------------- scratch (device globals) ------------------------------------
__device__ float g_u1[NN * DH];
__device__ float g_t1[NN * DH];
__device__ float g_h[NN * DH];
__device__ float g_m2[NN * DH];
__device__ float g_invdeg[NN];
__device__ int   g_degn[NN];       // zeroed by cleanup_kernel of the PREVIOUS call
__device__ int   g_off[NN];
__device__ int   g_cur[NN];
__device__ int   g_csr[NE];
__device__ int   g_total;          // zeroed by cleanup_kernel
__device__ float g_Sm[NG * DH];    // zeroed by cleanup_kernel
__device__ float g_Sh[NG * DH];    // zeroed by cleanup_kernel
__device__ float g_cnt[NG];        // zeroed by cleanup_kernel

__device__ __forceinline__ void red1(float* a, float v) {
    asm volatile("red.global.add.f32 [%0], %1;" :: "l"(a), "f"(v) : "memory");
}
__device__ __forceinline__ unsigned long long pack_dup(float a) {
    unsigned long long r;
    unsigned int ai = __float_as_uint(a);
    asm("mov.b64 %0, {%1, %1};" : "=l"(r) : "r"(ai));
    return r;
}
__device__ __forceinline__ void ffma2(unsigned long long& d,
                                      unsigned long long a, unsigned long long b) {
    asm("fma.rn.f32x2 %0, %1, %2, %0;" : "+l"(d) : "l"(a), "l"(b));
}
__device__ __forceinline__ void unpack2(unsigned long long p, float& x, float& y) {
    unsigned int lo, hi;
    asm("mov.b64 {%0, %1}, %2;" : "=r"(lo), "=r"(hi) : "l"(p));
    x = __uint_as_float(lo); y = __uint_as_float(hi);
}

// ---------------- GEMM tile body (f32x2 packed FMA) ----------------------------
// Computes rows [row0, row0+128): u1 = x@W1_l ; t1 = x@W1_r + b1
__device__ __forceinline__ void gemm_tile(
    const float* __restrict__ x, const float* __restrict__ Wl,
    const float* __restrict__ Wr, const float* __restrict__ b1, int row0)
{
    __shared__ float Xs[128][33];
    __shared__ float Ws[32][128];

    const int tid = threadIdx.x;
    const int ty = tid >> 4;
    const int tx = tid & 15;

    unsigned long long acc[8][4];
#pragma unroll
    for (int r = 0; r < 8; r++)
#pragma unroll
        for (int j = 0; j < 4; j++) acc[r][j] = 0ull;

    for (int k0 = 0; k0 < DIN; k0 += 32) {
#pragma unroll
        for (int p = 0; p < 4; p++) {
            int i = tid + p * 256;
            int row = i >> 3;
            int kq  = i & 7;
            float4 v = make_float4(0.f, 0.f, 0.f, 0.f);
            if (row0 + row < NN)
                v = *reinterpret_cast<const float4*>(
                        x + (size_t)(row0 + row) * DIN + k0 + kq * 4);
            Xs[row][kq * 4 + 0] = v.x;
            Xs[row][kq * 4 + 1] = v.y;
            Xs[row][kq * 4 + 2] = v.z;
            Xs[row][kq * 4 + 3] = v.w;
        }
#pragma unroll
        for (int p = 0; p < 4; p++) {
            int i = tid + p * 256;
            int k = i >> 5;
            int n = (i & 31) * 4;
            const float* sp = (n < DH) ? (Wl + (size_t)(k0 + k) * DH + n)
                                       : (Wr + (size_t)(k0 + k) * DH + (n - DH));
            *reinterpret_cast<float4*>(&Ws[k][n]) =
                *reinterpret_cast<const float4*>(sp);
        }
        __syncthreads();

#pragma unroll
        for (int k = 0; k < 32; k++) {
            unsigned long long bp[4];
#pragma unroll
            for (int jj = 0; jj < 4; jj++)
                bp[jj] = *reinterpret_cast<const unsigned long long*>(
                             &Ws[k][tx * 2 + 32 * jj]);
#pragma unroll
            for (int r = 0; r < 8; r++) {
                unsigned long long ap = pack_dup(Xs[ty * 8 + r][k]);
                ffma2(acc[r][0], ap, bp[0]);
                ffma2(acc[r][1], ap, bp[1]);
                ffma2(acc[r][2], ap, bp[2]);
                ffma2(acc[r][3], ap, bp[3]);
            }
        }
        __syncthreads();
    }

#pragma unroll
    for (int r = 0; r < 8; r++) {
        int row = row0 + ty * 8 + r;
        if (row >= NN) continue;
#pragma unroll
        for (int jj = 0; jj < 4; jj++) {
            int c = tx * 2 + 32 * jj;
            float v0, v1; unpack2(acc[r][jj], v0, v1);
            if (c < DH) {
                *reinterpret_cast<float2*>(g_u1 + (size_t)row * DH + c) =
                    make_float2(v0, v1);
            } else {
                int cc = c - DH;
                *reinterpret_cast<float2*>(g_t1 + (size_t)row * DH + cc) =
                    make_float2(v0 + b1[cc], v1 + b1[cc + 1]);
            }
        }
    }
}

// ---------------- fused kernel A: GEMM rows [0,50048) + degree histogram -------
__global__ __launch_bounds__(256) void gemmA_hist_kernel(
    const float* __restrict__ x, const float* __restrict__ Wl,
    const float* __restrict__ Wr, const float* __restrict__ b1,
    const int* __restrict__ ed)
{
    if (blockIdx.x < GEMM_A) {
        gemm_tile(x, Wl, Wr, b1, blockIdx.x * 128);
    } else {
        int base = (blockIdx.x - GEMM_A) * 256 + threadIdx.x;
#pragma unroll
        for (int j = 0; j < 4; j++) {
            int e = base + j * EDGE_STRIDE;
            if (e < NE) atomicAdd(&g_degn[ed[e]], 1);   // RED (no return)
        }
    }
}

// ---------------- scan: block-local exclusive scan + atomic block base ---------
__global__ __launch_bounds__(256) void scan_kernel() {
    __shared__ int sh[256];
    __shared__ int base_sh;
    int tid = threadIdx.x;
    int n = blockIdx.x * 256 + tid;
    int c = (n < NN) ? g_degn[n] : 0;
    sh[tid] = c; __syncthreads();
    for (int d = 1; d < 256; d <<= 1) {
        int t = (tid >= d) ? sh[tid - d] : 0;
        __syncthreads();
        sh[tid] += t;
        __syncthreads();
    }
    if (tid == 255) base_sh = atomicAdd(&g_total, sh[255]);
    __syncthreads();
    if (n < NN) {
        int off = base_sh + sh[tid] - c;
        g_off[n] = off;
        g_cur[n] = off;
        g_invdeg[n] = 1.0f / (float)max(c, 1);
    }
}

// ---------------- fused kernel B: GEMM rows [50048,NN) + CSR fill --------------
__global__ __launch_bounds__(256) void gemmB_fill_kernel(
    const float* __restrict__ x, const float* __restrict__ Wl,
    const float* __restrict__ Wr, const float* __restrict__ b1,
    const int* __restrict__ es, const int* __restrict__ ed)
{
    if (blockIdx.x >= EDGE_BLOCKS) {
        gemm_tile(x, Wl, Wr, b1, (GEMM_A + (blockIdx.x - EDGE_BLOCKS)) * 128);
    } else {
        int base = blockIdx.x * 256 + threadIdx.x;
        int e0 = base, e1 = base + EDGE_STRIDE,
            e2 = base + 2 * EDGE_STRIDE, e3 = base + 3 * EDGE_STRIDE;
        int d0 = (e0 < NE) ? ed[e0] : -1;
        int d1 = (e1 < NE) ? ed[e1] : -1;
        int d2 = (e2 < NE) ? ed[e2] : -1;
        int d3 = (e3 < NE) ? ed[e3] : -1;
        int p0 = (d0 >= 0) ? atomicAdd(&g_cur[d0], 1) : 0;
        int p1 = (d1 >= 0) ? atomicAdd(&g_cur[d1], 1) : 0;
        int p2 = (d2 >= 0) ? atomicAdd(&g_cur[d2], 1) : 0;
        int p3 = (d3 >= 0) ? atomicAdd(&g_cur[d3], 1) : 0;
        if (d0 >= 0) g_csr[p0] = es[e0];
        if (d1 >= 0) g_csr[p1] = es[e1];
        if (d2 >= 0) g_csr[p2] = es[e2];
        if (d3 >= 0) g_csr[p3] = es[e3];
    }
}

// ---------------- pull aggregation (CSR), fused epilogues ----------------------
__device__ __forceinline__ void acc4(float4& s, const float4& v) {
    s.x += v.x; s.y += v.y; s.z += v.z; s.w += v.w;
}

__global__ __launch_bounds__(256) void agg1_kernel() {
    int t = blockIdx.x * blockDim.x + threadIdx.x;
    int n = t >> 4;
    int lane = t & 15;
    if (n >= NN) return;
    int off = g_off[n];
    int deg = g_degn[n];
    const int* __restrict__ lst = g_csr + off;

    float4 s = make_float4(0.f, 0.f, 0.f, 0.f);
    int j = 0;
    for (; j + 8 <= deg; j += 8) {
        int i0 = lst[j],     i1 = lst[j + 1], i2 = lst[j + 2], i3 = lst[j + 3];
        int i4 = lst[j + 4], i5 = lst[j + 5], i6 = lst[j + 6], i7 = lst[j + 7];
        float4 v0 = *reinterpret_cast<const float4*>(g_u1 + (size_t)i0 * DH + lane * 4);
        float4 v1 = *reinterpret_cast<const float4*>(g_u1 + (size_t)i1 * DH + lane * 4);
        float4 v2 = *reinterpret_cast<const float4*>(g_u1 + (size_t)i2 * DH + lane * 4);
        float4 v3 = *reinterpret_cast<const float4*>(g_u1 + (size_t)i3 * DH + lane * 4);
        float4 v4 = *reinterpret_cast<const float4*>(g_u1 + (size_t)i4 * DH + lane * 4);
        float4 v5 = *reinterpret_cast<const float4*>(g_u1 + (size_t)i5 * DH + lane * 4);
        float4 v6 = *reinterpret_cast<const float4*>(g_u1 + (size_t)i6 * DH + lane * 4);
        float4 v7 = *reinterpret_cast<const float4*>(g_u1 + (size_t)i7 * DH + lane * 4);
        acc4(s, v0); acc4(s, v1); acc4(s, v2); acc4(s, v3);
        acc4(s, v4); acc4(s, v5); acc4(s, v6); acc4(s, v7);
    }
    for (; j < deg; j++) {
        float4 v = *reinterpret_cast<const float4*>(g_u1 + (size_t)lst[j] * DH + lane * 4);
        acc4(s, v);
    }
    float inv = g_invdeg[n];
    float4 tt = *reinterpret_cast<const float4*>(g_t1 + (size_t)n * DH + lane * 4);
    float4 h;
    h.x = fmaxf(fmaf(s.x, inv, tt.x), 0.f);
    h.y = fmaxf(fmaf(s.y, inv, tt.y), 0.f);
    h.z = fmaxf(fmaf(s.z, inv, tt.z), 0.f);
    h.w = fmaxf(fmaf(s.w, inv, tt.w), 0.f);
    *reinterpret_cast<float4*>(g_h + (size_t)n * DH + lane * 4) = h;
}

__global__ __launch_bounds__(256) void agg2_kernel() {
    int t = blockIdx.x * blockDim.x + threadIdx.x;
    int n = t >> 4;
    int lane = t & 15;
    if (n >= NN) return;
    int off = g_off[n];
    int deg = g_degn[n];
    const int* __restrict__ lst = g_csr + off;

    float4 s = make_float4(0.f, 0.f, 0.f, 0.f);
    int j = 0;
    for (; j + 8 <= deg; j += 8) {
        int i0 = lst[j],     i1 = lst[j + 1], i2 = lst[j + 2], i3 = lst[j + 3];
        int i4 = lst[j + 4], i5 = lst[j + 5], i6 = lst[j + 6], i7 = lst[j + 7];
        float4 v0 = *reinterpret_cast<const float4*>(g_h + (size_t)i0 * DH + lane * 4);
        float4 v1 = *reinterpret_cast<const float4*>(g_h + (size_t)i1 * DH + lane * 4);
        float4 v2 = *reinterpret_cast<const float4*>(g_h + (size_t)i2 * DH + lane * 4);
        float4 v3 = *reinterpret_cast<const float4*>(g_h + (size_t)i3 * DH + lane * 4);
        float4 v4 = *reinterpret_cast<const float4*>(g_h + (size_t)i4 * DH + lane * 4);
        float4 v5 = *reinterpret_cast<const float4*>(g_h + (size_t)i5 * DH + lane * 4);
        float4 v6 = *reinterpret_cast<const float4*>(g_h + (size_t)i6 * DH + lane * 4);
        float4 v7 = *reinterpret_cast<const float4*>(g_h + (size_t)i7 * DH + lane * 4);
        acc4(s, v0); acc4(s, v1); acc4(s, v2); acc4(s, v3);
        acc4(s, v4); acc4(s, v5); acc4(s, v6); acc4(s, v7);
    }
    for (; j < deg; j++) {
        float4 v = *reinterpret_cast<const float4*>(g_h + (size_t)lst[j] * DH + lane * 4);
        acc4(s, v);
    }
    float inv = g_invdeg[n];
    float4 m;
    m.x = s.x * inv; m.y = s.y * inv; m.z = s.z * inv; m.w = s.w * inv;
    *reinterpret_cast<float4*>(g_m2 + (size_t)n * DH + lane * 4) = m;
}

// ---------------- pooling (sorted batch_index, run-length accumulate) ----------
__global__ __launch_bounds__(128) void pool_kernel(const int* __restrict__ batch) {
    const int n0 = blockIdx.x * 128;
    const int nend = min(n0 + 128, NN);
    const int tid = threadIdx.x;
    const int c = tid & 63;
    const int which = tid >> 6;

    float local = 0.f;
    float cntloc = 0.f;
    int gcur = batch[n0];

    for (int n = n0; n < nend; n++) {
        int g = batch[n];
        if (g != gcur) {
            if (which == 0) red1(&g_Sh[gcur * DH + c], local);
            else            red1(&g_Sm[gcur * DH + c], local);
            if (tid == 0)   red1(&g_cnt[gcur], cntloc);
            local = 0.f; cntloc = 0.f; gcur = g;
        }
        float v = (which == 0) ? g_h[(size_t)n * DH + c]
                               : g_m2[(size_t)n * DH + c];
        local += v;
        cntloc += 1.f;
    }
    if (which == 0) red1(&g_Sh[gcur * DH + c], local);
    else            red1(&g_Sm[gcur * DH + c], local);
    if (tid == 0)   red1(&g_cnt[gcur], cntloc);
}

// out[g] = (Sm[g] @ W2_l + Sh[g] @ W2_r) / cnt[g] + b2
__global__ __launch_bounds__(128) void final_kernel(
    const float* __restrict__ W2l, const float* __restrict__ W2r,
    const float* __restrict__ b2, float* __restrict__ out)
{
    __shared__ float sm[DH], sh[DH];
    int g = blockIdx.x;
    int tid = threadIdx.x;
    if (tid < DH) {
        sm[tid] = g_Sm[g * DH + tid];
        sh[tid] = g_Sh[g * DH + tid];
    }
    __syncthreads();
    float a = 0.f;
#pragma unroll
    for (int k = 0; k < DH; k++) {
        a = fmaf(sm[k], W2l[(size_t)k * 128 + tid], a);
        a = fmaf(sh[k], W2r[(size_t)k * 128 + tid], a);
    }
    out[(size_t)g * 128 + tid] = a / fmaxf(g_cnt[g], 1.0f) + b2[tid];
}

// ---------------- cleanup: restore zero-invariant for the NEXT call ------------
__global__ void cleanup_kernel() {
    int i = blockIdx.x * blockDim.x + threadIdx.x;
    if (i < NN)      g_degn[i] = 0;
    if (i < NG * DH) { g_Sm[i] = 0.f; g_Sh[i] = 0.f; }
    if (i < NG)      g_cnt[i] = 0.f;
    if (i == 0)      g_total = 0;
}

// ---------------- launch ------------------------------------------------------
// ncu profiles launch index 3 -> agg1_kernel.
extern "C" void kernel_launch(void* const* d_in, const int* in_sizes, int n_in,
                              void* d_out, int out_size)
{
    const float* x    = (const float*)d_in[0];
    const float* W1l  = (const float*)d_in[1];
    const float* W1r  = (const float*)d_in[2];
    const float* b1   = (const float*)d_in[3];
    const float* W2l  = (const float*)d_in[4];
    const float* W2r  = (const float*)d_in[5];
    const float* b2   = (const float*)d_in[6];
    const int*   eidx = (const int*)d_in[7];
    const int*   batch= (const int*)d_in[8];
    float* out = (float*)d_out;

    const int* es = eidx;         // edge_index[0] (src)
    const int* ed = eidx + NE;    // edge_index[1] (dst)

    gemmA_hist_kernel<<<GEMM_A + EDGE_BLOCKS, 256>>>(x, W1l, W1r, b1, ed); // 0
    scan_kernel<<<NB, 256>>>();                                            // 1
    gemmB_fill_kernel<<<EDGE_BLOCKS + GEMM_B, 256>>>(x, W1l, W1r, b1, es, ed); // 2
    agg1_kernel<<<(NN * 16 + 255) / 256, 256>>>();                         // 3 <- ncu
    agg2_kernel<<<(NN * 16 + 255) / 256, 256>>>();                         // 4
    pool_kernel<<<(NN + 127) / 128, 128>>>(batch);                         // 5
    final_kernel<<<NG, 128>>>(W2l, W2r, b2, out);                          // 6
    cleanup_kernel<<<(NN + 255) / 256, 256>>>();                           // 7
}

// round 10
// speedup vs baseline: 1.1227x; 1.1227x over previous
#include <cuda_runtime.h>
#include <cuda_fp16.h>
#include <cstdint>

#define NN 100000
#define NE 1600000
#define DIN 128
#define DH 64
#define NG 512
#define NB 391              // ceil(NN/256)
#define EDGE_BLOCKS 1563    // ceil(NE/(256*4))
#define EDGE_STRIDE (EDGE_BLOCKS * 256)

// ---------------- scratch (device globals) ------------------------------------
__device__ __half g_u1h[NN * DH];  // x @ W1_l            (fp16 storage)
__device__ float  g_t1[NN * DH];   // x @ W1_r + b1       (fp32)
__device__ __half g_hh[NN * DH];   // layer-1 output      (fp16 storage)
__device__ __half g_m2h[NN * DH];  // layer-2 mean-agg    (fp16 storage)
__device__ float  g_invdeg[NN];
__device__ int    g_degn[NN];      // zeroed by cleanup_kernel of the PREVIOUS call
__device__ int    g_off[NN];
__device__ int    g_cur[NN];
__device__ int    g_csr[NE];
__device__ int    g_total;         // zeroed by cleanup_kernel
__device__ float  g_Sm[NG * DH];   // zeroed by cleanup_kernel
__device__ float  g_Sh[NG * DH];   // zeroed by cleanup_kernel
__device__ float  g_cnt[NG];       // zeroed by cleanup_kernel

__device__ __forceinline__ void red1(float* a, float v) {
    asm volatile("red.global.add.f32 [%0], %1;" :: "l"(a), "f"(v) : "memory");
}
__device__ __forceinline__ unsigned long long pack_dup(float a) {
    unsigned long long r;
    unsigned int ai = __float_as_uint(a);
    asm("mov.b64 %0, {%1, %1};" : "=l"(r) : "r"(ai));
    return r;
}
__device__ __forceinline__ void ffma2(unsigned long long& d,
                                      unsigned long long a, unsigned long long b) {
    asm("fma.rn.f32x2 %0, %1, %2, %0;" : "+l"(d) : "l"(a), "l"(b));
}
__device__ __forceinline__ void unpack2(unsigned long long p, float& x, float& y) {
    unsigned int lo, hi;
    asm("mov.b64 {%0, %1}, %2;" : "=r"(lo), "=r"(hi) : "l"(p));
    x = __uint_as_float(lo); y = __uint_as_float(hi);
}

// ---------------- CSR: histogram (MLP=4 unrolled atomics) ----------------------
__global__ __launch_bounds__(256) void hist_kernel(const int* __restrict__ ed) {
    int base = blockIdx.x * 256 + threadIdx.x;
#pragma unroll
    for (int j = 0; j < 4; j++) {
        int e = base + j * EDGE_STRIDE;
        if (e < NE) atomicAdd(&g_degn[ed[e]], 1);
    }
}

// ---------------- scan: block-local exclusive scan + atomic block base ---------
__global__ __launch_bounds__(256) void scan_kernel() {
    __shared__ int sh[256];
    __shared__ int base_sh;
    int tid = threadIdx.x;
    int n = blockIdx.x * 256 + tid;
    int c = (n < NN) ? g_degn[n] : 0;
    sh[tid] = c; __syncthreads();
    for (int d = 1; d < 256; d <<= 1) {
        int t = (tid >= d) ? sh[tid - d] : 0;
        __syncthreads();
        sh[tid] += t;
        __syncthreads();
    }
    if (tid == 255) base_sh = atomicAdd(&g_total, sh[255]);
    __syncthreads();
    if (n < NN) {
        int off = base_sh + sh[tid] - c;
        g_off[n] = off;
        g_cur[n] = off;
        g_invdeg[n] = 1.0f / (float)max(c, 1);
    }
}

// ---------------- CSR: fill (MLP=4 unrolled atomics) ---------------------------
__global__ __launch_bounds__(256) void fill_kernel(
    const int* __restrict__ es, const int* __restrict__ ed) {
    int base = blockIdx.x * 256 + threadIdx.x;
    int e0 = base, e1 = base + EDGE_STRIDE,
        e2 = base + 2 * EDGE_STRIDE, e3 = base + 3 * EDGE_STRIDE;
    int d0 = (e0 < NE) ? ed[e0] : -1;
    int d1 = (e1 < NE) ? ed[e1] : -1;
    int d2 = (e2 < NE) ? ed[e2] : -1;
    int d3 = (e3 < NE) ? ed[e3] : -1;
    int p0 = (d0 >= 0) ? atomicAdd(&g_cur[d0], 1) : 0;
    int p1 = (d1 >= 0) ? atomicAdd(&g_cur[d1], 1) : 0;
    int p2 = (d2 >= 0) ? atomicAdd(&g_cur[d2], 1) : 0;
    int p3 = (d3 >= 0) ? atomicAdd(&g_cur[d3], 1) : 0;
    if (d0 >= 0) g_csr[p0] = es[e0];
    if (d1 >= 0) g_csr[p1] = es[e1];
    if (d2 >= 0) g_csr[p2] = es[e2];
    if (d3 >= 0) g_csr[p3] = es[e3];
}

// ---------------- GEMM (f32x2): u1(fp16) = x@W1_l ; t1(fp32) = x@W1_r + b1 -----
__global__ __launch_bounds__(256) void gemm1_kernel(
    const float* __restrict__ x, const float* __restrict__ Wl,
    const float* __restrict__ Wr, const float* __restrict__ b1)
{
    __shared__ float Xs[128][33];
    __shared__ float Ws[32][128];

    const int tid = threadIdx.x;
    const int ty = tid >> 4;
    const int tx = tid & 15;
    const int row0 = blockIdx.x * 128;

    unsigned long long acc[8][4];
#pragma unroll
    for (int r = 0; r < 8; r++)
#pragma unroll
        for (int j = 0; j < 4; j++) acc[r][j] = 0ull;

    for (int k0 = 0; k0 < DIN; k0 += 32) {
#pragma unroll
        for (int p = 0; p < 4; p++) {
            int i = tid + p * 256;
            int row = i >> 3;
            int kq  = i & 7;
            float4 v = make_float4(0.f, 0.f, 0.f, 0.f);
            if (row0 + row < NN)
                v = *reinterpret_cast<const float4*>(
                        x + (size_t)(row0 + row) * DIN + k0 + kq * 4);
            Xs[row][kq * 4 + 0] = v.x;
            Xs[row][kq * 4 + 1] = v.y;
            Xs[row][kq * 4 + 2] = v.z;
            Xs[row][kq * 4 + 3] = v.w;
        }
#pragma unroll
        for (int p = 0; p < 4; p++) {
            int i = tid + p * 256;
            int k = i >> 5;
            int n = (i & 31) * 4;
            const float* sp = (n < DH) ? (Wl + (size_t)(k0 + k) * DH + n)
                                       : (Wr + (size_t)(k0 + k) * DH + (n - DH));
            *reinterpret_cast<float4*>(&Ws[k][n]) =
                *reinterpret_cast<const float4*>(sp);
        }
        __syncthreads();

#pragma unroll
        for (int k = 0; k < 32; k++) {
            unsigned long long bp[4];
#pragma unroll
            for (int jj = 0; jj < 4; jj++)
                bp[jj] = *reinterpret_cast<const unsigned long long*>(
                             &Ws[k][tx * 2 + 32 * jj]);
#pragma unroll
            for (int r = 0; r < 8; r++) {
                unsigned long long ap = pack_dup(Xs[ty * 8 + r][k]);
                ffma2(acc[r][0], ap, bp[0]);
                ffma2(acc[r][1], ap, bp[1]);
                ffma2(acc[r][2], ap, bp[2]);
                ffma2(acc[r][3], ap, bp[3]);
            }
        }
        __syncthreads();
    }

#pragma unroll
    for (int r = 0; r < 8; r++) {
        int row = row0 + ty * 8 + r;
        if (row >= NN) continue;
#pragma unroll
        for (int jj = 0; jj < 4; jj++) {
            int c = tx * 2 + 32 * jj;
            float v0, v1; unpack2(acc[r][jj], v0, v1);
            if (c < DH) {
                *reinterpret_cast<__half2*>(g_u1h + (size_t)row * DH + c) =
                    __floats2half2_rn(v0, v1);
            } else {
                int cc = c - DH;
                *reinterpret_cast<float2*>(g_t1 + (size_t)row * DH + cc) =
                    make_float2(v0 + b1[cc], v1 + b1[cc + 1]);
            }
        }
    }
}

// ---------------- pull aggregation (fp16 gathers, fp32 math) -------------------
// 8 lanes per node; each lane owns 8 features (one uint4 = 8 halves).
__device__ __forceinline__ void acc_h8(float* s, uint4 w) {
    float2 f0 = __half22float2(*reinterpret_cast<__half2*>(&w.x));
    float2 f1 = __half22float2(*reinterpret_cast<__half2*>(&w.y));
    float2 f2 = __half22float2(*reinterpret_cast<__half2*>(&w.z));
    float2 f3 = __half22float2(*reinterpret_cast<__half2*>(&w.w));
    s[0] += f0.x; s[1] += f0.y; s[2] += f1.x; s[3] += f1.y;
    s[4] += f2.x; s[5] += f2.y; s[6] += f3.x; s[7] += f3.y;
}

__global__ __launch_bounds__(256) void agg1_kernel() {
    int t = blockIdx.x * blockDim.x + threadIdx.x;
    int n = t >> 3;
    int lane = t & 7;
    if (n >= NN) return;
    int off = g_off[n];
    int deg = g_degn[n];
    const int* __restrict__ lst = g_csr + off;

    float s[8];
#pragma unroll
    for (int q = 0; q < 8; q++) s[q] = 0.f;

    int j = 0;
    for (; j + 4 <= deg; j += 4) {
        int i0 = lst[j], i1 = lst[j + 1], i2 = lst[j + 2], i3 = lst[j + 3];
        uint4 w0 = reinterpret_cast<const uint4*>(g_u1h + (size_t)i0 * DH)[lane];
        uint4 w1 = reinterpret_cast<const uint4*>(g_u1h + (size_t)i1 * DH)[lane];
        uint4 w2 = reinterpret_cast<const uint4*>(g_u1h + (size_t)i2 * DH)[lane];
        uint4 w3 = reinterpret_cast<const uint4*>(g_u1h + (size_t)i3 * DH)[lane];
        acc_h8(s, w0); acc_h8(s, w1); acc_h8(s, w2); acc_h8(s, w3);
    }
    for (; j < deg; j++) {
        uint4 w = reinterpret_cast<const uint4*>(g_u1h + (size_t)lst[j] * DH)[lane];
        acc_h8(s, w);
    }

    float inv = g_invdeg[n];
    const float* trow = g_t1 + (size_t)n * DH + lane * 8;
    float4 ta = *reinterpret_cast<const float4*>(trow);
    float4 tb = *reinterpret_cast<const float4*>(trow + 4);
    float h[8];
    h[0] = fmaxf(fmaf(s[0], inv, ta.x), 0.f);
    h[1] = fmaxf(fmaf(s[1], inv, ta.y), 0.f);
    h[2] = fmaxf(fmaf(s[2], inv, ta.z), 0.f);
    h[3] = fmaxf(fmaf(s[3], inv, ta.w), 0.f);
    h[4] = fmaxf(fmaf(s[4], inv, tb.x), 0.f);
    h[5] = fmaxf(fmaf(s[5], inv, tb.y), 0.f);
    h[6] = fmaxf(fmaf(s[6], inv, tb.z), 0.f);
    h[7] = fmaxf(fmaf(s[7], inv, tb.w), 0.f);

    uint4 o;
    *reinterpret_cast<__half2*>(&o.x) = __floats2half2_rn(h[0], h[1]);
    *reinterpret_cast<__half2*>(&o.y) = __floats2half2_rn(h[2], h[3]);
    *reinterpret_cast<__half2*>(&o.z) = __floats2half2_rn(h[4], h[5]);
    *reinterpret_cast<__half2*>(&o.w) = __floats2half2_rn(h[6], h[7]);
    reinterpret_cast<uint4*>(g_hh + (size_t)n * DH)[lane] = o;
}

__global__ __launch_bounds__(256) void agg2_kernel() {
    int t = blockIdx.x * blockDim.x + threadIdx.x;
    int n = t >> 3;
    int lane = t & 7;
    if (n >= NN) return;
    int off = g_off[n];
    int deg = g_degn[n];
    const int* __restrict__ lst = g_csr + off;

    float s[8];
#pragma unroll
    for (int q = 0; q < 8; q++) s[q] = 0.f;

    int j = 0;
    for (; j + 4 <= deg; j += 4) {
        int i0 = lst[j], i1 = lst[j + 1], i2 = lst[j + 2], i3 = lst[j + 3];
        uint4 w0 = reinterpret_cast<const uint4*>(g_hh + (size_t)i0 * DH)[lane];
        uint4 w1 = reinterpret_cast<const uint4*>(g_hh + (size_t)i1 * DH)[lane];
        uint4 w2 = reinterpret_cast<const uint4*>(g_hh + (size_t)i2 * DH)[lane];
        uint4 w3 = reinterpret_cast<const uint4*>(g_hh + (size_t)i3 * DH)[lane];
        acc_h8(s, w0); acc_h8(s, w1); acc_h8(s, w2); acc_h8(s, w3);
    }
    for (; j < deg; j++) {
        uint4 w = reinterpret_cast<const uint4*>(g_hh + (size_t)lst[j] * DH)[lane];
        acc_h8(s, w);
    }

    float inv = g_invdeg[n];
    uint4 o;
    *reinterpret_cast<__half2*>(&o.x) = __floats2half2_rn(s[0] * inv, s[1] * inv);
    *reinterpret_cast<__half2*>(&o.y) = __floats2half2_rn(s[2] * inv, s[3] * inv);
    *reinterpret_cast<__half2*>(&o.z) = __floats2half2_rn(s[4] * inv, s[5] * inv);
    *reinterpret_cast<__half2*>(&o.w) = __floats2half2_rn(s[6] * inv, s[7] * inv);
    reinterpret_cast<uint4*>(g_m2h + (size_t)n * DH)[lane] = o;
}

// ---------------- pooling (sorted batch_index, run-length accumulate) ----------
__global__ __launch_bounds__(128) void pool_kernel(const int* __restrict__ batch) {
    const int n0 = blockIdx.x * 128;
    const int nend = min(n0 + 128, NN);
    const int tid = threadIdx.x;
    const int c = tid & 63;
    const int which = tid >> 6;     // 0 -> Sh (h), 1 -> Sm (m2)

    float local = 0.f;
    float cntloc = 0.f;
    int gcur = batch[n0];

    for (int n = n0; n < nend; n++) {
        int g = batch[n];
        if (g != gcur) {
            if (which == 0) red1(&g_Sh[gcur * DH + c], local);
            else            red1(&g_Sm[gcur * DH + c], local);
            if (tid == 0)   red1(&g_cnt[gcur], cntloc);
            local = 0.f; cntloc = 0.f; gcur = g;
        }
        float v = (which == 0) ? __half2float(g_hh[(size_t)n * DH + c])
                               : __half2float(g_m2h[(size_t)n * DH + c]);
        local += v;
        cntloc += 1.f;
    }
    if (which == 0) red1(&g_Sh[gcur * DH + c], local);
    else            red1(&g_Sm[gcur * DH + c], local);
    if (tid == 0)   red1(&g_cnt[gcur], cntloc);
}

// out[g] = (Sm[g] @ W2_l + Sh[g] @ W2_r) / cnt[g] + b2
__global__ __launch_bounds__(128) void final_kernel(
    const float* __restrict__ W2l, const float* __restrict__ W2r,
    const float* __restrict__ b2, float* __restrict__ out)
{
    __shared__ float sm[DH], sh[DH];
    int g = blockIdx.x;
    int tid = threadIdx.x;
    if (tid < DH) {
        sm[tid] = g_Sm[g * DH + tid];
        sh[tid] = g_Sh[g * DH + tid];
    }
    __syncthreads();
    float a = 0.f;
#pragma unroll
    for (int k = 0; k < DH; k++) {
        a = fmaf(sm[k], W2l[(size_t)k * 128 + tid], a);
        a = fmaf(sh[k], W2r[(size_t)k * 128 + tid], a);
    }
    out[(size_t)g * 128 + tid] = a / fmaxf(g_cnt[g], 1.0f) + b2[tid];
}

// ---------------- cleanup: restore zero-invariant for the NEXT call ------------
__global__ void cleanup_kernel() {
    int i = blockIdx.x * blockDim.x + threadIdx.x;
    if (i < NN)      g_degn[i] = 0;
    if (i < NG * DH) { g_Sm[i] = 0.f; g_Sh[i] = 0.f; }
    if (i < NG)      g_cnt[i] = 0.f;
    if (i == 0)      g_total = 0;
}

// ---------------- launch ------------------------------------------------------
// ncu profiles launch index 3 -> gemm1_kernel.
extern "C" void kernel_launch(void* const* d_in, const int* in_sizes, int n_in,
                              void* d_out, int out_size)
{
    const float* x    = (const float*)d_in[0];
    const float* W1l  = (const float*)d_in[1];
    const float* W1r  = (const float*)d_in[2];
    const float* b1   = (const float*)d_in[3];
    const float* W2l  = (const float*)d_in[4];
    const float* W2r  = (const float*)d_in[5];
    const float* b2   = (const float*)d_in[6];
    const int*   eidx = (const int*)d_in[7];
    const int*   batch= (const int*)d_in[8];
    float* out = (float*)d_out;

    const int* es = eidx;         // edge_index[0] (src)
    const int* ed = eidx + NE;    // edge_index[1] (dst)

    hist_kernel<<<EDGE_BLOCKS, 256>>>(ed);                       // 0
    scan_kernel<<<NB, 256>>>();                                  // 1
    fill_kernel<<<EDGE_BLOCKS, 256>>>(es, ed);                   // 2
    gemm1_kernel<<<(NN + 127) / 128, 256>>>(x, W1l, W1r, b1);    // 3 <- ncu
    agg1_kernel<<<(NN * 8 + 255) / 256, 256>>>();                // 4
    agg2_kernel<<<(NN * 8 + 255) / 256, 256>>>();                // 5
    pool_kernel<<<(NN + 127) / 128, 128>>>(batch);               // 6
    final_kernel<<<NG, 128>>>(W2l, W2r, b2, out);                // 7
    cleanup_kernel<<<(NN + 255) / 256, 256>>>();                 // 8
}

// round 12
// speedup vs baseline: 1.1988x; 1.0678x over previous
#include <cuda_runtime.h>
#include <cuda_fp16.h>
#include <cstdint>

#define NN 100000
#define NE 1600000
#define DIN 128
#define DH 64
#define NG 512
#define NB 391              // ceil(NN/256)
#define EDGE_BLOCKS 1563    // ceil(NE/(256*4))
#define EDGE_STRIDE (EDGE_BLOCKS * 256)
#define GROWS 64
#define GEMM_GRID 1563      // ceil(NN/64)

// ---------------- scratch (device globals) ------------------------------------
__device__ __half g_u1h[NN * DH];  // x @ W1_l            (fp16 storage)
__device__ float  g_t1[NN * DH];   // x @ W1_r + b1       (fp32)
__device__ __half g_hh[NN * DH];   // layer-1 output      (fp16 storage)
__device__ __half g_m2h[NN * DH];  // layer-2 mean-agg    (fp16 storage)
__device__ float  g_invdeg[NN];
__device__ int    g_degn[NN];      // zeroed by cleanup_kernel of the PREVIOUS call
__device__ int    g_off[NN];
__device__ int    g_cur[NN];
__device__ int    g_csr[NE];
__device__ int    g_total;         // zeroed by cleanup_kernel
__device__ float  g_Sm[NG * DH];   // zeroed by cleanup_kernel
__device__ float  g_Sh[NG * DH];   // zeroed by cleanup_kernel
__device__ float  g_cnt[NG];       // zeroed by cleanup_kernel

__device__ __forceinline__ void red1(float* a, float v) {
    asm volatile("red.global.add.f32 [%0], %1;" :: "l"(a), "f"(v) : "memory");
}
__device__ __forceinline__ unsigned long long pack_dup(float a) {
    unsigned long long r;
    unsigned int ai = __float_as_uint(a);
    asm("mov.b64 %0, {%1, %1};" : "=l"(r) : "r"(ai));
    return r;
}
__device__ __forceinline__ void ffma2(unsigned long long& d,
                                      unsigned long long a, unsigned long long b) {
    asm("fma.rn.f32x2 %0, %1, %2, %0;" : "+l"(d) : "l"(a), "l"(b));
}
__device__ __forceinline__ void unpack2(unsigned long long p, float& x, float& y) {
    unsigned int lo, hi;
    asm("mov.b64 {%0, %1}, %2;" : "=r"(lo), "=r"(hi) : "l"(p));
    x = __uint_as_float(lo); y = __uint_as_float(hi);
}

// ---------------- CSR: histogram (MLP=4 unrolled atomics) ----------------------
__global__ __launch_bounds__(256) void hist_kernel(const int* __restrict__ ed) {
    int base = blockIdx.x * 256 + threadIdx.x;
#pragma unroll
    for (int j = 0; j < 4; j++) {
        int e = base + j * EDGE_STRIDE;
        if (e < NE) atomicAdd(&g_degn[ed[e]], 1);
    }
}

// ---------------- scan: block-local exclusive scan + atomic block base ---------
__global__ __launch_bounds__(256) void scan_kernel() {
    __shared__ int sh[256];
    __shared__ int base_sh;
    int tid = threadIdx.x;
    int n = blockIdx.x * 256 + tid;
    int c = (n < NN) ? g_degn[n] : 0;
    sh[tid] = c; __syncthreads();
    for (int d = 1; d < 256; d <<= 1) {
        int t = (tid >= d) ? sh[tid - d] : 0;
        __syncthreads();
        sh[tid] += t;
        __syncthreads();
    }
    if (tid == 255) base_sh = atomicAdd(&g_total, sh[255]);
    __syncthreads();
    if (n < NN) {
        int off = base_sh + sh[tid] - c;
        g_off[n] = off;
        g_cur[n] = off;
        g_invdeg[n] = 1.0f / (float)max(c, 1);
    }
}

// ---------------- CSR: fill (MLP=4 unrolled atomics) ---------------------------
__global__ __launch_bounds__(256) void fill_kernel(
    const int* __restrict__ es, const int* __restrict__ ed) {
    int base = blockIdx.x * 256 + threadIdx.x;
    int e0 = base, e1 = base + EDGE_STRIDE,
        e2 = base + 2 * EDGE_STRIDE, e3 = base + 3 * EDGE_STRIDE;
    int d0 = (e0 < NE) ? ed[e0] : -1;
    int d1 = (e1 < NE) ? ed[e1] : -1;
    int d2 = (e2 < NE) ? ed[e2] : -1;
    int d3 = (e3 < NE) ? ed[e3] : -1;
    int p0 = (d0 >= 0) ? atomicAdd(&g_cur[d0], 1) : 0;
    int p1 = (d1 >= 0) ? atomicAdd(&g_cur[d1], 1) : 0;
    int p2 = (d2 >= 0) ? atomicAdd(&g_cur[d2], 1) : 0;
    int p3 = (d3 >= 0) ? atomicAdd(&g_cur[d3], 1) : 0;
    if (d0 >= 0) g_csr[p0] = es[e0];
    if (d1 >= 0) g_csr[p1] = es[e1];
    if (d2 >= 0) g_csr[p2] = es[e2];
    if (d3 >= 0) g_csr[p3] = es[e3];
}

// ---------------- GEMM (f32x2), 64-row tile, full-K shared, sync-free mainloop -
// u1(fp16) = x@W1_l ; t1(fp32) = x@W1_r + b1
// 256 threads: ty=tid>>4 -> rows ty*4..+3 ; tx=tid&15 -> col pairs {tx*2+32j}
__global__ __launch_bounds__(256) void gemm1_kernel(
    const float* __restrict__ x, const float* __restrict__ Wl,
    const float* __restrict__ Wr, const float* __restrict__ b1)
{
    __shared__ float Xs[GROWS][DIN + 4];   // 64 x 132 (pad keeps row-k reads conflict-free)
    __shared__ float Ws[DIN][128];         // [k][col]; col<64 -> Wl, col>=64 -> Wr

    const int tid = threadIdx.x;
    const int ty = tid >> 4;
    const int tx = tid & 15;
    const int row0 = blockIdx.x * GROWS;

    // Load W block: 128x128 floats = 4096 float4, 16 per thread.
#pragma unroll
    for (int p = 0; p < 16; p++) {
        int i = tid + p * 256;          // float4 index 0..4095
        int k = i >> 5;                 // 32 float4 per k-row
        int n = (i & 31) * 4;
        const float* sp = (n < DH) ? (Wl + (size_t)k * DH + n)
                                   : (Wr + (size_t)k * DH + (n - DH));
        *reinterpret_cast<float4*>(&Ws[k][n]) =
            *reinterpret_cast<const float4*>(sp);
    }
    // Load X tile: 64x128 floats = 2048 float4, 8 per thread.
#pragma unroll
    for (int p = 0; p < 8; p++) {
        int i = tid + p * 256;          // float4 index 0..2047
        int row = i >> 5;
        int kq = (i & 31) * 4;
        float4 v = make_float4(0.f, 0.f, 0.f, 0.f);
        if (row0 + row < NN)
            v = *reinterpret_cast<const float4*>(
                    x + (size_t)(row0 + row) * DIN + kq);
        Xs[row][kq + 0] = v.x;
        Xs[row][kq + 1] = v.y;
        Xs[row][kq + 2] = v.z;
        Xs[row][kq + 3] = v.w;
    }
    __syncthreads();

    unsigned long long acc[4][4];
#pragma unroll
    for (int r = 0; r < 4; r++)
#pragma unroll
        for (int j = 0; j < 4; j++) acc[r][j] = 0ull;

#pragma unroll 4
    for (int k = 0; k < DIN; k++) {
        unsigned long long bp[4];
#pragma unroll
        for (int jj = 0; jj < 4; jj++)
            bp[jj] = *reinterpret_cast<const unsigned long long*>(
                         &Ws[k][tx * 2 + 32 * jj]);
#pragma unroll
        for (int r = 0; r < 4; r++) {
            unsigned long long ap = pack_dup(Xs[ty * 4 + r][k]);
            ffma2(acc[r][0], ap, bp[0]);
            ffma2(acc[r][1], ap, bp[1]);
            ffma2(acc[r][2], ap, bp[2]);
            ffma2(acc[r][3], ap, bp[3]);
        }
    }

#pragma unroll
    for (int r = 0; r < 4; r++) {
        int row = row0 + ty * 4 + r;
        if (row >= NN) continue;
#pragma unroll
        for (int jj = 0; jj < 4; jj++) {
            int c = tx * 2 + 32 * jj;
            float v0, v1; unpack2(acc[r][jj], v0, v1);
            if (c < DH) {
                *reinterpret_cast<__half2*>(g_u1h + (size_t)row * DH + c) =
                    __floats2half2_rn(v0, v1);
            } else {
                int cc = c - DH;
                *reinterpret_cast<float2*>(g_t1 + (size_t)row * DH + cc) =
                    make_float2(v0 + b1[cc], v1 + b1[cc + 1]);
            }
        }
    }
}

// ---------------- pull aggregation (fp16 gathers, fp32 math) -------------------
// 8 lanes per node; each lane owns 8 features (one uint4 = 8 halves).
__device__ __forceinline__ void acc_h8(float* s, uint4 w) {
    float2 f0 = __half22float2(*reinterpret_cast<__half2*>(&w.x));
    float2 f1 = __half22float2(*reinterpret_cast<__half2*>(&w.y));
    float2 f2 = __half22float2(*reinterpret_cast<__half2*>(&w.z));
    float2 f3 = __half22float2(*reinterpret_cast<__half2*>(&w.w));
    s[0] += f0.x; s[1] += f0.y; s[2] += f1.x; s[3] += f1.y;
    s[4] += f2.x; s[5] += f2.y; s[6] += f3.x; s[7] += f3.y;
}

__global__ __launch_bounds__(256) void agg1_kernel() {
    int t = blockIdx.x * blockDim.x + threadIdx.x;
    int n = t >> 3;
    int lane = t & 7;
    if (n >= NN) return;
    int off = g_off[n];
    int deg = g_degn[n];
    const int* __restrict__ lst = g_csr + off;

    float s[8];
#pragma unroll
    for (int q = 0; q < 8; q++) s[q] = 0.f;

    int j = 0;
    for (; j + 4 <= deg; j += 4) {
        int i0 = lst[j], i1 = lst[j + 1], i2 = lst[j + 2], i3 = lst[j + 3];
        uint4 w0 = reinterpret_cast<const uint4*>(g_u1h + (size_t)i0 * DH)[lane];
        uint4 w1 = reinterpret_cast<const uint4*>(g_u1h + (size_t)i1 * DH)[lane];
        uint4 w2 = reinterpret_cast<const uint4*>(g_u1h + (size_t)i2 * DH)[lane];
        uint4 w3 = reinterpret_cast<const uint4*>(g_u1h + (size_t)i3 * DH)[lane];
        acc_h8(s, w0); acc_h8(s, w1); acc_h8(s, w2); acc_h8(s, w3);
    }
    for (; j < deg; j++) {
        uint4 w = reinterpret_cast<const uint4*>(g_u1h + (size_t)lst[j] * DH)[lane];
        acc_h8(s, w);
    }

    float inv = g_invdeg[n];
    const float* trow = g_t1 + (size_t)n * DH + lane * 8;
    float4 ta = *reinterpret_cast<const float4*>(trow);
    float4 tb = *reinterpret_cast<const float4*>(trow + 4);
    float h[8];
    h[0] = fmaxf(fmaf(s[0], inv, ta.x), 0.f);
    h[1] = fmaxf(fmaf(s[1], inv, ta.y), 0.f);
    h[2] = fmaxf(fmaf(s[2], inv, ta.z), 0.f);
    h[3] = fmaxf(fmaf(s[3], inv, ta.w), 0.f);
    h[4] = fmaxf(fmaf(s[4], inv, tb.x), 0.f);
    h[5] = fmaxf(fmaf(s[5], inv, tb.y), 0.f);
    h[6] = fmaxf(fmaf(s[6], inv, tb.z), 0.f);
    h[7] = fmaxf(fmaf(s[7], inv, tb.w), 0.f);

    uint4 o;
    *reinterpret_cast<__half2*>(&o.x) = __floats2half2_rn(h[0], h[1]);
    *reinterpret_cast<__half2*>(&o.y) = __floats2half2_rn(h[2], h[3]);
    *reinterpret_cast<__half2*>(&o.z) = __floats2half2_rn(h[4], h[5]);
    *reinterpret_cast<__half2*>(&o.w) = __floats2half2_rn(h[6], h[7]);
    reinterpret_cast<uint4*>(g_hh + (size_t)n * DH)[lane] = o;
}

__global__ __launch_bounds__(256) void agg2_kernel() {
    int t = blockIdx.x * blockDim.x + threadIdx.x;
    int n = t >> 3;
    int lane = t & 7;
    if (n >= NN) return;
    int off = g_off[n];
    int deg = g_degn[n];
    const int* __restrict__ lst = g_csr + off;

    float s[8];
#pragma unroll
    for (int q = 0; q < 8; q++) s[q] = 0.f;

    int j = 0;
    for (; j + 4 <= deg; j += 4) {
        int i0 = lst[j], i1 = lst[j + 1], i2 = lst[j + 2], i3 = lst[j + 3];
        uint4 w0 = reinterpret_cast<const uint4*>(g_hh + (size_t)i0 * DH)[lane];
        uint4 w1 = reinterpret_cast<const uint4*>(g_hh + (size_t)i1 * DH)[lane];
        uint4 w2 = reinterpret_cast<const uint4*>(g_hh + (size_t)i2 * DH)[lane];
        uint4 w3 = reinterpret_cast<const uint4*>(g_hh + (size_t)i3 * DH)[lane];
        acc_h8(s, w0); acc_h8(s, w1); acc_h8(s, w2); acc_h8(s, w3);
    }
    for (; j < deg; j++) {
        uint4 w = reinterpret_cast<const uint4*>(g_hh + (size_t)lst[j] * DH)[lane];
        acc_h8(s, w);
    }

    float inv = g_invdeg[n];
    uint4 o;
    *reinterpret_cast<__half2*>(&o.x) = __floats2half2_rn(s[0] * inv, s[1] * inv);
    *reinterpret_cast<__half2*>(&o.y) = __floats2half2_rn(s[2] * inv, s[3] * inv);
    *reinterpret_cast<__half2*>(&o.z) = __floats2half2_rn(s[4] * inv, s[5] * inv);
    *reinterpret_cast<__half2*>(&o.w) = __floats2half2_rn(s[6] * inv, s[7] * inv);
    reinterpret_cast<uint4*>(g_m2h + (size_t)n * DH)[lane] = o;
}

// ---------------- pooling (sorted batch_index, run-length accumulate) ----------
__global__ __launch_bounds__(128) void pool_kernel(const int* __restrict__ batch) {
    const int n0 = blockIdx.x * 128;
    const int nend = min(n0 + 128, NN);
    const int tid = threadIdx.x;
    const int c = tid & 63;
    const int which = tid >> 6;     // 0 -> Sh (h), 1 -> Sm (m2)

    float local = 0.f;
    float cntloc = 0.f;
    int gcur = batch[n0];

    for (int n = n0; n < nend; n++) {
        int g = batch[n];
        if (g != gcur) {
            if (which == 0) red1(&g_Sh[gcur * DH + c], local);
            else            red1(&g_Sm[gcur * DH + c], local);
            if (tid == 0)   red1(&g_cnt[gcur], cntloc);
            local = 0.f; cntloc = 0.f; gcur = g;
        }
        float v = (which == 0) ? __half2float(g_hh[(size_t)n * DH + c])
                               : __half2float(g_m2h[(size_t)n * DH + c]);
        local += v;
        cntloc += 1.f;
    }
    if (which == 0) red1(&g_Sh[gcur * DH + c], local);
    else            red1(&g_Sm[gcur * DH + c], local);
    if (tid == 0)   red1(&g_cnt[gcur], cntloc);
}

// out[g] = (Sm[g] @ W2_l + Sh[g] @ W2_r) / cnt[g] + b2
__global__ __launch_bounds__(128) void final_kernel(
    const float* __restrict__ W2l, const float* __restrict__ W2r,
    const float* __restrict__ b2, float* __restrict__ out)
{
    __shared__ float sm[DH], sh[DH];
    int g = blockIdx.x;
    int tid = threadIdx.x;
    if (tid < DH) {
        sm[tid] = g_Sm[g * DH + tid];
        sh[tid] = g_Sh[g * DH + tid];
    }
    __syncthreads();
    float a = 0.f;
#pragma unroll
    for (int k = 0; k < DH; k++) {
        a = fmaf(sm[k], W2l[(size_t)k * 128 + tid], a);
        a = fmaf(sh[k], W2r[(size_t)k * 128 + tid], a);
    }
    out[(size_t)g * 128 + tid] = a / fmaxf(g_cnt[g], 1.0f) + b2[tid];
}

// ---------------- cleanup: restore zero-invariant for the NEXT call ------------
__global__ void cleanup_kernel() {
    int i = blockIdx.x * blockDim.x + threadIdx.x;
    if (i < NN)      g_degn[i] = 0;
    if (i < NG * DH) { g_Sm[i] = 0.f; g_Sh[i] = 0.f; }
    if (i < NG)      g_cnt[i] = 0.f;
    if (i == 0)      g_total = 0;
}

// ---------------- launch ------------------------------------------------------
// ncu profiles launch index 3 -> gemm1_kernel (verify occupancy fix).
extern "C" void kernel_launch(void* const* d_in, const int* in_sizes, int n_in,
                              void* d_out, int out_size)
{
    const float* x    = (const float*)d_in[0];
    const float* W1l  = (const float*)d_in[1];
    const float* W1r  = (const float*)d_in[2];
    const float* b1   = (const float*)d_in[3];
    const float* W2l  = (const float*)d_in[4];
    const float* W2r  = (const float*)d_in[5];
    const float* b2   = (const float*)d_in[6];
    const int*   eidx = (const int*)d_in[7];
    const int*   batch= (const int*)d_in[8];
    float* out = (float*)d_out;

    const int* es = eidx;         // edge_index[0] (src)
    const int* ed = eidx + NE;    // edge_index[1] (dst)

    hist_kernel<<<EDGE_BLOCKS, 256>>>(ed);                       // 0
    scan_kernel<<<NB, 256>>>();                                  // 1
    fill_kernel<<<EDGE_BLOCKS, 256>>>(es, ed);                   // 2
    gemm1_kernel<<<GEMM_GRID, 256>>>(x, W1l, W1r, b1);           // 3 <- ncu
    agg1_kernel<<<(NN * 8 + 255) / 256, 256>>>();                // 4
    agg2_kernel<<<(NN * 8 + 255) / 256, 256>>>();                // 5
    pool_kernel<<<(NN + 127) / 128, 128>>>(batch);               // 6
    final_kernel<<<NG, 128>>>(W2l, W2r, b2, out);                // 7
    cleanup_kernel<<<(NN + 255) / 256, 256>>>();                 // 8
}

// round 14
// speedup vs baseline: 1.3963x; 1.1648x over previous
#include <cuda_runtime.h>
#include <cuda_fp16.h>
#include <cstdint>

#define NN 100000
#define NE 1600000
#define DIN 128
#define DH 64
#define NG 512
#define NB 391              // ceil(NN/256)
#define EDGE_BLOCKS 1563    // ceil(NE/(256*4))
#define EDGE_STRIDE (EDGE_BLOCKS * 256)
#define GROWS 64
#define GEMM_GRID 1563      // ceil(NN/64)
#define NP 132              // padded smem row stride (words)

// ---------------- scratch (device globals) ------------------------------------
__device__ __half g_u1h[NN * DH];  // x @ W1_l            (fp16 storage)
__device__ float  g_t1[NN * DH];   // x @ W1_r + b1       (fp32)
__device__ __half g_hh[NN * DH];   // layer-1 output      (fp16 storage)
__device__ __half g_m2h[NN * DH];  // layer-2 mean-agg    (fp16 storage)
__device__ float  g_invdeg[NN];
__device__ int    g_degn[NN];      // zeroed by cleanup_kernel of the PREVIOUS call
__device__ int    g_off[NN];
__device__ int    g_cur[NN];
__device__ int    g_csr[NE];
__device__ int    g_total;         // zeroed by cleanup_kernel
__device__ float  g_Sm[NG * DH];   // zeroed by cleanup_kernel
__device__ float  g_Sh[NG * DH];   // zeroed by cleanup_kernel
__device__ float  g_cnt[NG];       // zeroed by cleanup_kernel

__device__ __forceinline__ void red1(float* a, float v) {
    asm volatile("red.global.add.f32 [%0], %1;" :: "l"(a), "f"(v) : "memory");
}
__device__ __forceinline__ uint32_t f2tf(float f) {
    uint32_t r; asm("cvt.rna.tf32.f32 %0, %1;" : "=r"(r) : "f"(f)); return r;
}
__device__ __forceinline__ void mma_tf32(float* d, const uint32_t* a,
                                         uint32_t b0, uint32_t b1) {
    asm volatile(
        "mma.sync.aligned.m16n8k8.row.col.f32.tf32.tf32.f32 "
        "{%0,%1,%2,%3}, {%4,%5,%6,%7}, {%8,%9}, {%0,%1,%2,%3};"
        : "+f"(d[0]), "+f"(d[1]), "+f"(d[2]), "+f"(d[3])
        : "r"(a[0]), "r"(a[1]), "r"(a[2]), "r"(a[3]), "r"(b0), "r"(b1));
}

// ---------------- CSR: histogram (MLP=4 unrolled atomics) ----------------------
__global__ __launch_bounds__(256) void hist_kernel(const int* __restrict__ ed) {
    int base = blockIdx.x * 256 + threadIdx.x;
#pragma unroll
    for (int j = 0; j < 4; j++) {
        int e = base + j * EDGE_STRIDE;
        if (e < NE) atomicAdd(&g_degn[ed[e]], 1);
    }
}

// ---------------- scan: block-local exclusive scan + atomic block base ---------
__global__ __launch_bounds__(256) void scan_kernel() {
    __shared__ int sh[256];
    __shared__ int base_sh;
    int tid = threadIdx.x;
    int n = blockIdx.x * 256 + tid;
    int c = (n < NN) ? g_degn[n] : 0;
    sh[tid] = c; __syncthreads();
    for (int d = 1; d < 256; d <<= 1) {
        int t = (tid >= d) ? sh[tid - d] : 0;
        __syncthreads();
        sh[tid] += t;
        __syncthreads();
    }
    if (tid == 255) base_sh = atomicAdd(&g_total, sh[255]);
    __syncthreads();
    if (n < NN) {
        int off = base_sh + sh[tid] - c;
        g_off[n] = off;
        g_cur[n] = off;
        g_invdeg[n] = 1.0f / (float)max(c, 1);
    }
}

// ---------------- CSR: fill (MLP=4 unrolled atomics) ---------------------------
__global__ __launch_bounds__(256) void fill_kernel(
    const int* __restrict__ es, const int* __restrict__ ed) {
    int base = blockIdx.x * 256 + threadIdx.x;
    int e0 = base, e1 = base + EDGE_STRIDE,
        e2 = base + 2 * EDGE_STRIDE, e3 = base + 3 * EDGE_STRIDE;
    int d0 = (e0 < NE) ? ed[e0] : -1;
    int d1 = (e1 < NE) ? ed[e1] : -1;
    int d2 = (e2 < NE) ? ed[e2] : -1;
    int d3 = (e3 < NE) ? ed[e3] : -1;
    int p0 = (d0 >= 0) ? atomicAdd(&g_cur[d0], 1) : 0;
    int p1 = (d1 >= 0) ? atomicAdd(&g_cur[d1], 1) : 0;
    int p2 = (d2 >= 0) ? atomicAdd(&g_cur[d2], 1) : 0;
    int p3 = (d3 >= 0) ? atomicAdd(&g_cur[d3], 1) : 0;
    if (d0 >= 0) g_csr[p0] = es[e0];
    if (d1 >= 0) g_csr[p1] = es[e1];
    if (d2 >= 0) g_csr[p2] = es[e2];
    if (d3 >= 0) g_csr[p3] = es[e3];
}

// ---------------- GEMM (tf32 mma.sync): u1(fp16)=x@W1_l ; t1(fp32)=x@W1_r+b1 ---
// 64-row x 128-col tile, 256 threads = 8 warps (2 along M x 4 along N).
// Warp tile: 32 rows x 32 cols = 2 m-atoms x 4 n-atoms of m16n8k8, 16 k-steps.
__global__ __launch_bounds__(256) void gemm1_kernel(
    const float* __restrict__ x, const float* __restrict__ Wl,
    const float* __restrict__ Wr, const float* __restrict__ bias1)
{
    __shared__ uint32_t Xs[GROWS][NP];   // 64 x 132 tf32
    __shared__ uint32_t Ws[DIN][NP];     // 128 x 132 tf32 (k-major)

    const int tid = threadIdx.x;
    const int row0 = blockIdx.x * GROWS;

    // Load W block (tf32): 4096 float4, 16 per thread.
#pragma unroll
    for (int p = 0; p < 16; p++) {
        int i = tid + p * 256;
        int k = i >> 5;
        int n = (i & 31) * 4;
        const float* sp = (n < DH) ? (Wl + (size_t)k * DH + n)
                                   : (Wr + (size_t)k * DH + (n - DH));
        float4 v = *reinterpret_cast<const float4*>(sp);
        uint4 w = make_uint4(f2tf(v.x), f2tf(v.y), f2tf(v.z), f2tf(v.w));
        *reinterpret_cast<uint4*>(&Ws[k][n]) = w;
    }
    // Load X tile (tf32): 2048 float4, 8 per thread.
#pragma unroll
    for (int p = 0; p < 8; p++) {
        int i = tid + p * 256;
        int row = i >> 5;
        int kq = (i & 31) * 4;
        float4 v = make_float4(0.f, 0.f, 0.f, 0.f);
        if (row0 + row < NN)
            v = *reinterpret_cast<const float4*>(
                    x + (size_t)(row0 + row) * DIN + kq);
        uint4 w = make_uint4(f2tf(v.x), f2tf(v.y), f2tf(v.z), f2tf(v.w));
        *reinterpret_cast<uint4*>(&Xs[row][kq]) = w;
    }
    __syncthreads();

    const int wid = tid >> 5;
    const int lane = tid & 31;
    const int mw = wid & 1;          // row half: 0 or 1 (32 rows each)
    const int nwp = wid >> 1;        // col quarter: 0..3 (32 cols each)
    const int g = lane >> 2;         // 0..7
    const int t = lane & 3;          // 0..3

    float acc[2][4][4];
#pragma unroll
    for (int ma = 0; ma < 2; ma++)
#pragma unroll
        for (int na = 0; na < 4; na++)
#pragma unroll
            for (int q = 0; q < 4; q++) acc[ma][na][q] = 0.f;

#pragma unroll 4
    for (int ks = 0; ks < 16; ks++) {
        int k0 = ks * 8;
        uint32_t a[2][4];
#pragma unroll
        for (int ma = 0; ma < 2; ma++) {
            int r0 = mw * 32 + ma * 16 + g;
            a[ma][0] = Xs[r0][k0 + t];
            a[ma][1] = Xs[r0 + 8][k0 + t];
            a[ma][2] = Xs[r0][k0 + t + 4];
            a[ma][3] = Xs[r0 + 8][k0 + t + 4];
        }
#pragma unroll
        for (int na = 0; na < 4; na++) {
            int c0 = nwp * 32 + na * 8 + g;
            uint32_t b0 = Ws[k0 + t][c0];
            uint32_t b1f = Ws[k0 + t + 4][c0];
            mma_tf32(acc[0][na], a[0], b0, b1f);
            mma_tf32(acc[1][na], a[1], b0, b1f);
        }
    }

    // Epilogue: D frag c0/c1 at (row, 2t/2t+1), c2/c3 at (row+8, ...).
#pragma unroll
    for (int ma = 0; ma < 2; ma++) {
        int rbase = row0 + mw * 32 + ma * 16 + g;
#pragma unroll
        for (int na = 0; na < 4; na++) {
            int c = nwp * 32 + na * 8 + 2 * t;
#pragma unroll
            for (int h = 0; h < 2; h++) {
                int row = rbase + h * 8;
                if (row >= NN) continue;
                float v0 = acc[ma][na][h * 2 + 0];
                float v1 = acc[ma][na][h * 2 + 1];
                if (c < DH) {
                    *reinterpret_cast<__half2*>(g_u1h + (size_t)row * DH + c) =
                        __floats2half2_rn(v0, v1);
                } else {
                    int cc = c - DH;
                    *reinterpret_cast<float2*>(g_t1 + (size_t)row * DH + cc) =
                        make_float2(v0 + bias1[cc], v1 + bias1[cc + 1]);
                }
            }
        }
    }
}

// ---------------- pull aggregation (fp16 gathers, fp32 math) -------------------
// 8 lanes per node; each lane owns 8 features (one uint4 = 8 halves).
__device__ __forceinline__ void acc_h8(float* s, uint4 w) {
    float2 f0 = __half22float2(*reinterpret_cast<__half2*>(&w.x));
    float2 f1 = __half22float2(*reinterpret_cast<__half2*>(&w.y));
    float2 f2 = __half22float2(*reinterpret_cast<__half2*>(&w.z));
    float2 f3 = __half22float2(*reinterpret_cast<__half2*>(&w.w));
    s[0] += f0.x; s[1] += f0.y; s[2] += f1.x; s[3] += f1.y;
    s[4] += f2.x; s[5] += f2.y; s[6] += f3.x; s[7] += f3.y;
}

__global__ __launch_bounds__(256) void agg1_kernel() {
    int t = blockIdx.x * blockDim.x + threadIdx.x;
    int n = t >> 3;
    int lane = t & 7;
    if (n >= NN) return;
    int off = g_off[n];
    int deg = g_degn[n];
    const int* __restrict__ lst = g_csr + off;

    float s[8];
#pragma unroll
    for (int q = 0; q < 8; q++) s[q] = 0.f;

    int j = 0;
    for (; j + 4 <= deg; j += 4) {
        int i0 = lst[j], i1 = lst[j + 1], i2 = lst[j + 2], i3 = lst[j + 3];
        uint4 w0 = reinterpret_cast<const uint4*>(g_u1h + (size_t)i0 * DH)[lane];
        uint4 w1 = reinterpret_cast<const uint4*>(g_u1h + (size_t)i1 * DH)[lane];
        uint4 w2 = reinterpret_cast<const uint4*>(g_u1h + (size_t)i2 * DH)[lane];
        uint4 w3 = reinterpret_cast<const uint4*>(g_u1h + (size_t)i3 * DH)[lane];
        acc_h8(s, w0); acc_h8(s, w1); acc_h8(s, w2); acc_h8(s, w3);
    }
    for (; j < deg; j++) {
        uint4 w = reinterpret_cast<const uint4*>(g_u1h + (size_t)lst[j] * DH)[lane];
        acc_h8(s, w);
    }

    float inv = g_invdeg[n];
    const float* trow = g_t1 + (size_t)n * DH + lane * 8;
    float4 ta = *reinterpret_cast<const float4*>(trow);
    float4 tb = *reinterpret_cast<const float4*>(trow + 4);
    float h[8];
    h[0] = fmaxf(fmaf(s[0], inv, ta.x), 0.f);
    h[1] = fmaxf(fmaf(s[1], inv, ta.y), 0.f);
    h[2] = fmaxf(fmaf(s[2], inv, ta.z), 0.f);
    h[3] = fmaxf(fmaf(s[3], inv, ta.w), 0.f);
    h[4] = fmaxf(fmaf(s[4], inv, tb.x), 0.f);
    h[5] = fmaxf(fmaf(s[5], inv, tb.y), 0.f);
    h[6] = fmaxf(fmaf(s[6], inv, tb.z), 0.f);
    h[7] = fmaxf(fmaf(s[7], inv, tb.w), 0.f);

    uint4 o;
    *reinterpret_cast<__half2*>(&o.x) = __floats2half2_rn(h[0], h[1]);
    *reinterpret_cast<__half2*>(&o.y) = __floats2half2_rn(h[2], h[3]);
    *reinterpret_cast<__half2*>(&o.z) = __floats2half2_rn(h[4], h[5]);
    *reinterpret_cast<__half2*>(&o.w) = __floats2half2_rn(h[6], h[7]);
    reinterpret_cast<uint4*>(g_hh + (size_t)n * DH)[lane] = o;
}

__global__ __launch_bounds__(256) void agg2_kernel() {
    int t = blockIdx.x * blockDim.x + threadIdx.x;
    int n = t >> 3;
    int lane = t & 7;
    if (n >= NN) return;
    int off = g_off[n];
    int deg = g_degn[n];
    const int* __restrict__ lst = g_csr + off;

    float s[8];
#pragma unroll
    for (int q = 0; q < 8; q++) s[q] = 0.f;

    int j = 0;
    for (; j + 4 <= deg; j += 4) {
        int i0 = lst[j], i1 = lst[j + 1], i2 = lst[j + 2], i3 = lst[j + 3];
        uint4 w0 = reinterpret_cast<const uint4*>(g_hh + (size_t)i0 * DH)[lane];
        uint4 w1 = reinterpret_cast<const uint4*>(g_hh + (size_t)i1 * DH)[lane];
        uint4 w2 = reinterpret_cast<const uint4*>(g_hh + (size_t)i2 * DH)[lane];
        uint4 w3 = reinterpret_cast<const uint4*>(g_hh + (size_t)i3 * DH)[lane];
        acc_h8(s, w0); acc_h8(s, w1); acc_h8(s, w2); acc_h8(s, w3);
    }
    for (; j < deg; j++) {
        uint4 w = reinterpret_cast<const uint4*>(g_hh + (size_t)lst[j] * DH)[lane];
        acc_h8(s, w);
    }

    float inv = g_invdeg[n];
    uint4 o;
    *reinterpret_cast<__half2*>(&o.x) = __floats2half2_rn(s[0] * inv, s[1] * inv);
    *reinterpret_cast<__half2*>(&o.y) = __floats2half2_rn(s[2] * inv, s[3] * inv);
    *reinterpret_cast<__half2*>(&o.z) = __floats2half2_rn(s[4] * inv, s[5] * inv);
    *reinterpret_cast<__half2*>(&o.w) = __floats2half2_rn(s[6] * inv, s[7] * inv);
    reinterpret_cast<uint4*>(g_m2h + (size_t)n * DH)[lane] = o;
}

// ---------------- pooling (sorted batch_index, run-length accumulate) ----------
__global__ __launch_bounds__(128) void pool_kernel(const int* __restrict__ batch) {
    const int n0 = blockIdx.x * 128;
    const int nend = min(n0 + 128, NN);
    const int tid = threadIdx.x;
    const int c = tid & 63;
    const int which = tid >> 6;     // 0 -> Sh (h), 1 -> Sm (m2)

    float local = 0.f;
    float cntloc = 0.f;
    int gcur = batch[n0];

    for (int n = n0; n < nend; n++) {
        int g = batch[n];
        if (g != gcur) {
            if (which == 0) red1(&g_Sh[gcur * DH + c], local);
            else            red1(&g_Sm[gcur * DH + c], local);
            if (tid == 0)   red1(&g_cnt[gcur], cntloc);
            local = 0.f; cntloc = 0.f; gcur = g;
        }
        float v = (which == 0) ? __half2float(g_hh[(size_t)n * DH + c])
                               : __half2float(g_m2h[(size_t)n * DH + c]);
        local += v;
        cntloc += 1.f;
    }
    if (which == 0) red1(&g_Sh[gcur * DH + c], local);
    else            red1(&g_Sm[gcur * DH + c], local);
    if (tid == 0)   red1(&g_cnt[gcur], cntloc);
}

// out[g] = (Sm[g] @ W2_l + Sh[g] @ W2_r) / cnt[g] + b2
__global__ __launch_bounds__(128) void final_kernel(
    const float* __restrict__ W2l, const float* __restrict__ W2r,
    const float* __restrict__ b2, float* __restrict__ out)
{
    __shared__ float sm[DH], sh[DH];
    int g = blockIdx.x;
    int tid = threadIdx.x;
    if (tid < DH) {
        sm[tid] = g_Sm[g * DH + tid];
        sh[tid] = g_Sh[g * DH + tid];
    }
    __syncthreads();
    float a = 0.f;
#pragma unroll
    for (int k = 0; k < DH; k++) {
        a = fmaf(sm[k], W2l[(size_t)k * 128 + tid], a);
        a = fmaf(sh[k], W2r[(size_t)k * 128 + tid], a);
    }
    out[(size_t)g * 128 + tid] = a / fmaxf(g_cnt[g], 1.0f) + b2[tid];
}

// ---------------- cleanup: restore zero-invariant for the NEXT call ------------
__global__ void cleanup_kernel() {
    int i = blockIdx.x * blockDim.x + threadIdx.x;
    if (i < NN)      g_degn[i] = 0;
    if (i < NG * DH) { g_Sm[i] = 0.f; g_Sh[i] = 0.f; }
    if (i < NG)      g_cnt[i] = 0.f;
    if (i == 0)      g_total = 0;
}

// ---------------- launch ------------------------------------------------------
// ncu profiles launch index 3 -> gemm1_kernel (verify tensor-pipe engagement).
extern "C" void kernel_launch(void* const* d_in, const int* in_sizes, int n_in,
                              void* d_out, int out_size)
{
    const float* x    = (const float*)d_in[0];
    const float* W1l  = (const float*)d_in[1];
    const float* W1r  = (const float*)d_in[2];
    const float* b1   = (const float*)d_in[3];
    const float* W2l  = (const float*)d_in[4];
    const float* W2r  = (const float*)d_in[5];
    const float* b2   = (const float*)d_in[6];
    const int*   eidx = (const int*)d_in[7];
    const int*   batch= (const int*)d_in[8];
    float* out = (float*)d_out;

    const int* es = eidx;         // edge_index[0] (src)
    const int* ed = eidx + NE;    // edge_index[1] (dst)

    hist_kernel<<<EDGE_BLOCKS, 256>>>(ed);                       // 0
    scan_kernel<<<NB, 256>>>();                                  // 1
    fill_kernel<<<EDGE_BLOCKS, 256>>>(es, ed);                   // 2
    gemm1_kernel<<<GEMM_GRID, 256>>>(x, W1l, W1r, b1);           // 3 <- ncu
    agg1_kernel<<<(NN * 8 + 255) / 256, 256>>>();                // 4
    agg2_kernel<<<(NN * 8 + 255) / 256, 256>>>();                // 5
    pool_kernel<<<(NN + 127) / 128, 128>>>(batch);               // 6
    final_kernel<<<NG, 128>>>(W2l, W2r, b2, out);                // 7
    cleanup_kernel<<<(NN + 255) / 256, 256>>>();                 // 8
}

// round 15
// speedup vs baseline: 1.4890x; 1.0664x over previous
#include <cuda_runtime.h>
#include <cuda_fp16.h>
#include <cuda_bf16.h>
#include <cstdint>

#define NN 100000
#define NE 1600000
#define DIN 128
#define DH 64
#define NG 512
#define NB 391              // ceil(NN/256)
#define EDGE_BLOCKS 1563    // ceil(NE/(256*4))
#define EDGE_STRIDE (EDGE_BLOCKS * 256)
#define GROWS 64
#define GEMM_GRID 1563      // ceil(NN/64)
#define XP 136              // padded bf16 row stride (16B-aligned, conflict-free LDSM)

// ---------------- scratch (device globals) ------------------------------------
__device__ __half g_u1h[NN * DH];  // x @ W1_l            (fp16 storage)
__device__ float  g_t1[NN * DH];   // x @ W1_r + b1       (fp32)
__device__ __half g_hh[NN * DH];   // layer-1 output      (fp16 storage)
__device__ __half g_m2h[NN * DH];  // layer-2 mean-agg    (fp16 storage)
__device__ float  g_invdeg[NN];
__device__ int    g_degn[NN];      // zeroed by cleanup_kernel of the PREVIOUS call
__device__ int    g_off[NN];
__device__ int    g_cur[NN];
__device__ int    g_csr[NE];
__device__ int    g_total;         // zeroed by cleanup_kernel
__device__ float  g_Sm[NG * DH];   // zeroed by cleanup_kernel
__device__ float  g_Sh[NG * DH];   // zeroed by cleanup_kernel
__device__ float  g_cnt[NG];       // zeroed by cleanup_kernel

__device__ __forceinline__ void red1(float* a, float v) {
    asm volatile("red.global.add.f32 [%0], %1;" :: "l"(a), "f"(v) : "memory");
}
__device__ __forceinline__ uint32_t bf2pack(float lo, float hi) {
    __nv_bfloat162 p = __floats2bfloat162_rn(lo, hi);
    return *reinterpret_cast<uint32_t*>(&p);
}
__device__ __forceinline__ void ldsm_x4(uint32_t* d, uint32_t addr) {
    asm volatile("ldmatrix.sync.aligned.m8n8.x4.shared.b16 {%0,%1,%2,%3}, [%4];"
        : "=r"(d[0]), "=r"(d[1]), "=r"(d[2]), "=r"(d[3]) : "r"(addr));
}
__device__ __forceinline__ void ldsm_x4_t(uint32_t* d, uint32_t addr) {
    asm volatile("ldmatrix.sync.aligned.m8n8.x4.trans.shared.b16 {%0,%1,%2,%3}, [%4];"
        : "=r"(d[0]), "=r"(d[1]), "=r"(d[2]), "=r"(d[3]) : "r"(addr));
}
__device__ __forceinline__ void mma_bf16(float* d, const uint32_t* a,
                                         uint32_t b0, uint32_t b1) {
    asm volatile(
        "mma.sync.aligned.m16n8k16.row.col.f32.bf16.bf16.f32 "
        "{%0,%1,%2,%3}, {%4,%5,%6,%7}, {%8,%9}, {%0,%1,%2,%3};"
        : "+f"(d[0]), "+f"(d[1]), "+f"(d[2]), "+f"(d[3])
        : "r"(a[0]), "r"(a[1]), "r"(a[2]), "r"(a[3]), "r"(b0), "r"(b1));
}

// ---------------- CSR: histogram (MLP=4 unrolled atomics) ----------------------
__global__ __launch_bounds__(256) void hist_kernel(const int* __restrict__ ed) {
    int base = blockIdx.x * 256 + threadIdx.x;
#pragma unroll
    for (int j = 0; j < 4; j++) {
        int e = base + j * EDGE_STRIDE;
        if (e < NE) atomicAdd(&g_degn[ed[e]], 1);
    }
}

// ---------------- scan: block-local exclusive scan + atomic block base ---------
__global__ __launch_bounds__(256) void scan_kernel() {
    __shared__ int sh[256];
    __shared__ int base_sh;
    int tid = threadIdx.x;
    int n = blockIdx.x * 256 + tid;
    int c = (n < NN) ? g_degn[n] : 0;
    sh[tid] = c; __syncthreads();
    for (int d = 1; d < 256; d <<= 1) {
        int t = (tid >= d) ? sh[tid - d] : 0;
        __syncthreads();
        sh[tid] += t;
        __syncthreads();
    }
    if (tid == 255) base_sh = atomicAdd(&g_total, sh[255]);
    __syncthreads();
    if (n < NN) {
        int off = base_sh + sh[tid] - c;
        g_off[n] = off;
        g_cur[n] = off;
        g_invdeg[n] = 1.0f / (float)max(c, 1);
    }
}

// ---------------- CSR: fill (MLP=4 unrolled atomics) ---------------------------
__global__ __launch_bounds__(256) void fill_kernel(
    const int* __restrict__ es, const int* __restrict__ ed) {
    int base = blockIdx.x * 256 + threadIdx.x;
    int e0 = base, e1 = base + EDGE_STRIDE,
        e2 = base + 2 * EDGE_STRIDE, e3 = base + 3 * EDGE_STRIDE;
    int d0 = (e0 < NE) ? ed[e0] : -1;
    int d1 = (e1 < NE) ? ed[e1] : -1;
    int d2 = (e2 < NE) ? ed[e2] : -1;
    int d3 = (e3 < NE) ? ed[e3] : -1;
    int p0 = (d0 >= 0) ? atomicAdd(&g_cur[d0], 1) : 0;
    int p1 = (d1 >= 0) ? atomicAdd(&g_cur[d1], 1) : 0;
    int p2 = (d2 >= 0) ? atomicAdd(&g_cur[d2], 1) : 0;
    int p3 = (d3 >= 0) ? atomicAdd(&g_cur[d3], 1) : 0;
    if (d0 >= 0) g_csr[p0] = es[e0];
    if (d1 >= 0) g_csr[p1] = es[e1];
    if (d2 >= 0) g_csr[p2] = es[e2];
    if (d3 >= 0) g_csr[p3] = es[e3];
}

// ---------------- GEMM (bf16 mma + ldmatrix): u1(fp16)=x@W1_l ; t1=x@W1_r+b1 ---
// 64x128 tile, 8 warps (2 M x 4 N). Warp tile 32x32 = 2 m-atoms x 4 n-atoms of
// m16n8k16, 8 k-steps. Per k-step: 2 LDSM.x4 (A) + 2 LDSM.x4.trans (B) + 8 MMA.
__global__ __launch_bounds__(256) void gemm1_kernel(
    const float* __restrict__ x, const float* __restrict__ Wl,
    const float* __restrict__ Wr, const float* __restrict__ bias1)
{
    __shared__ __nv_bfloat16 Xs[GROWS][XP];   // 64 x 136 bf16 (272B stride)
    __shared__ __nv_bfloat16 Ws[DIN][XP];     // 128 x 136 bf16 (k-major)

    const int tid = threadIdx.x;
    const int row0 = blockIdx.x * GROWS;

    // Load W block (bf16): 4096 float4, 16 per thread -> uint2 stores.
#pragma unroll
    for (int p = 0; p < 16; p++) {
        int i = tid + p * 256;
        int k = i >> 5;
        int n = (i & 31) * 4;
        const float* sp = (n < DH) ? (Wl + (size_t)k * DH + n)
                                   : (Wr + (size_t)k * DH + (n - DH));
        float4 v = *reinterpret_cast<const float4*>(sp);
        uint2 w = make_uint2(bf2pack(v.x, v.y), bf2pack(v.z, v.w));
        *reinterpret_cast<uint2*>(&Ws[k][n]) = w;
    }
    // Load X tile (bf16): 2048 float4, 8 per thread.
#pragma unroll
    for (int p = 0; p < 8; p++) {
        int i = tid + p * 256;
        int row = i >> 5;
        int kq = (i & 31) * 4;
        float4 v = make_float4(0.f, 0.f, 0.f, 0.f);
        if (row0 + row < NN)
            v = *reinterpret_cast<const float4*>(
                    x + (size_t)(row0 + row) * DIN + kq);
        uint2 w = make_uint2(bf2pack(v.x, v.y), bf2pack(v.z, v.w));
        *reinterpret_cast<uint2*>(&Xs[row][kq]) = w;
    }
    __syncthreads();

    const int wid = tid >> 5;
    const int lane = tid & 31;
    const int mw = wid & 1;          // row half (32 rows each)
    const int nwp = wid >> 1;        // col quarter (32 cols each)
    const int q = lane >> 3;         // ldmatrix quadrant 0..3
    const int r = lane & 7;          // row within quadrant
    const int g = lane >> 2;         // mma frag row
    const int t = lane & 3;          // mma frag col group

    // ldmatrix source row/col offsets (quadrants: {Q00,Q10,Q01,Q11})
    const int qr = (q & 1) * 8 + r;  // +0/+8 row within 16
    const int qc = (q >> 1) * 8;     // +0/+8 col

    float acc[2][4][4];
#pragma unroll
    for (int ma = 0; ma < 2; ma++)
#pragma unroll
        for (int na = 0; na < 4; na++)
#pragma unroll
            for (int z = 0; z < 4; z++) acc[ma][na][z] = 0.f;

#pragma unroll
    for (int ks = 0; ks < 8; ks++) {
        int k0 = ks * 16;
        uint32_t a[2][4];
#pragma unroll
        for (int ma = 0; ma < 2; ma++) {
            uint32_t addr = (uint32_t)__cvta_generic_to_shared(
                &Xs[mw * 32 + ma * 16 + qr][k0 + qc]);
            ldsm_x4(a[ma], addr);
        }
        uint32_t b[2][4];
#pragma unroll
        for (int nb = 0; nb < 2; nb++) {
            uint32_t addr = (uint32_t)__cvta_generic_to_shared(
                &Ws[k0 + qr][nwp * 32 + nb * 16 + qc]);
            ldsm_x4_t(b[nb], addr);
        }
#pragma unroll
        for (int na = 0; na < 4; na++) {
            uint32_t b0 = b[na >> 1][(na & 1) * 2 + 0];
            uint32_t b1 = b[na >> 1][(na & 1) * 2 + 1];
            mma_bf16(acc[0][na], a[0], b0, b1);
            mma_bf16(acc[1][na], a[1], b0, b1);
        }
    }

    // Epilogue: D frag c0/c1 at (row g, cols 2t/2t+1), c2/c3 at (row g+8).
#pragma unroll
    for (int ma = 0; ma < 2; ma++) {
        int rbase = row0 + mw * 32 + ma * 16 + g;
#pragma unroll
        for (int na = 0; na < 4; na++) {
            int c = nwp * 32 + na * 8 + 2 * t;
#pragma unroll
            for (int h = 0; h < 2; h++) {
                int row = rbase + h * 8;
                if (row >= NN) continue;
                float v0 = acc[ma][na][h * 2 + 0];
                float v1 = acc[ma][na][h * 2 + 1];
                if (c < DH) {
                    *reinterpret_cast<__half2*>(g_u1h + (size_t)row * DH + c) =
                        __floats2half2_rn(v0, v1);
                } else {
                    int cc = c - DH;
                    *reinterpret_cast<float2*>(g_t1 + (size_t)row * DH + cc) =
                        make_float2(v0 + bias1[cc], v1 + bias1[cc + 1]);
                }
            }
        }
    }
}

// ---------------- pull aggregation (fp16 gathers, fp32 math) -------------------
// 8 lanes per node; each lane owns 8 features (one uint4 = 8 halves).
__device__ __forceinline__ void acc_h8(float* s, uint4 w) {
    float2 f0 = __half22float2(*reinterpret_cast<__half2*>(&w.x));
    float2 f1 = __half22float2(*reinterpret_cast<__half2*>(&w.y));
    float2 f2 = __half22float2(*reinterpret_cast<__half2*>(&w.z));
    float2 f3 = __half22float2(*reinterpret_cast<__half2*>(&w.w));
    s[0] += f0.x; s[1] += f0.y; s[2] += f1.x; s[3] += f1.y;
    s[4] += f2.x; s[5] += f2.y; s[6] += f3.x; s[7] += f3.y;
}

__global__ __launch_bounds__(256) void agg1_kernel() {
    int t = blockIdx.x * blockDim.x + threadIdx.x;
    int n = t >> 3;
    int lane = t & 7;
    if (n >= NN) return;
    int off = g_off[n];
    int deg = g_degn[n];
    const int* __restrict__ lst = g_csr + off;

    float s[8];
#pragma unroll
    for (int q = 0; q < 8; q++) s[q] = 0.f;

    int j = 0;
    for (; j + 4 <= deg; j += 4) {
        int i0 = lst[j], i1 = lst[j + 1], i2 = lst[j + 2], i3 = lst[j + 3];
        uint4 w0 = reinterpret_cast<const uint4*>(g_u1h + (size_t)i0 * DH)[lane];
        uint4 w1 = reinterpret_cast<const uint4*>(g_u1h + (size_t)i1 * DH)[lane];
        uint4 w2 = reinterpret_cast<const uint4*>(g_u1h + (size_t)i2 * DH)[lane];
        uint4 w3 = reinterpret_cast<const uint4*>(g_u1h + (size_t)i3 * DH)[lane];
        acc_h8(s, w0); acc_h8(s, w1); acc_h8(s, w2); acc_h8(s, w3);
    }
    for (; j < deg; j++) {
        uint4 w = reinterpret_cast<const uint4*>(g_u1h + (size_t)lst[j] * DH)[lane];
        acc_h8(s, w);
    }

    float inv = g_invdeg[n];
    const float* trow = g_t1 + (size_t)n * DH + lane * 8;
    float4 ta = *reinterpret_cast<const float4*>(trow);
    float4 tb = *reinterpret_cast<const float4*>(trow + 4);
    float h[8];
    h[0] = fmaxf(fmaf(s[0], inv, ta.x), 0.f);
    h[1] = fmaxf(fmaf(s[1], inv, ta.y), 0.f);
    h[2] = fmaxf(fmaf(s[2], inv, ta.z), 0.f);
    h[3] = fmaxf(fmaf(s[3], inv, ta.w), 0.f);
    h[4] = fmaxf(fmaf(s[4], inv, tb.x), 0.f);
    h[5] = fmaxf(fmaf(s[5], inv, tb.y), 0.f);
    h[6] = fmaxf(fmaf(s[6], inv, tb.z), 0.f);
    h[7] = fmaxf(fmaf(s[7], inv, tb.w), 0.f);

    uint4 o;
    *reinterpret_cast<__half2*>(&o.x) = __floats2half2_rn(h[0], h[1]);
    *reinterpret_cast<__half2*>(&o.y) = __floats2half2_rn(h[2], h[3]);
    *reinterpret_cast<__half2*>(&o.z) = __floats2half2_rn(h[4], h[5]);
    *reinterpret_cast<__half2*>(&o.w) = __floats2half2_rn(h[6], h[7]);
    reinterpret_cast<uint4*>(g_hh + (size_t)n * DH)[lane] = o;
}

__global__ __launch_bounds__(256) void agg2_kernel() {
    int t = blockIdx.x * blockDim.x + threadIdx.x;
    int n = t >> 3;
    int lane = t & 7;
    if (n >= NN) return;
    int off = g_off[n];
    int deg = g_degn[n];
    const int* __restrict__ lst = g_csr + off;

    float s[8];
#pragma unroll
    for (int q = 0; q < 8; q++) s[q] = 0.f;

    int j = 0;
    for (; j + 4 <= deg; j += 4) {
        int i0 = lst[j], i1 = lst[j + 1], i2 = lst[j + 2], i3 = lst[j + 3];
        uint4 w0 = reinterpret_cast<const uint4*>(g_hh + (size_t)i0 * DH)[lane];
        uint4 w1 = reinterpret_cast<const uint4*>(g_hh + (size_t)i1 * DH)[lane];
        uint4 w2 = reinterpret_cast<const uint4*>(g_hh + (size_t)i2 * DH)[lane];
        uint4 w3 = reinterpret_cast<const uint4*>(g_hh + (size_t)i3 * DH)[lane];
        acc_h8(s, w0); acc_h8(s, w1); acc_h8(s, w2); acc_h8(s, w3);
    }
    for (; j < deg; j++) {
        uint4 w = reinterpret_cast<const uint4*>(g_hh + (size_t)lst[j] * DH)[lane];
        acc_h8(s, w);
    }

    float inv = g_invdeg[n];
    uint4 o;
    *reinterpret_cast<__half2*>(&o.x) = __floats2half2_rn(s[0] * inv, s[1] * inv);
    *reinterpret_cast<__half2*>(&o.y) = __floats2half2_rn(s[2] * inv, s[3] * inv);
    *reinterpret_cast<__half2*>(&o.z) = __floats2half2_rn(s[4] * inv, s[5] * inv);
    *reinterpret_cast<__half2*>(&o.w) = __floats2half2_rn(s[6] * inv, s[7] * inv);
    reinterpret_cast<uint4*>(g_m2h + (size_t)n * DH)[lane] = o;
}

// ---------------- pooling (sorted batch_index, run-length accumulate) ----------
__global__ __launch_bounds__(128) void pool_kernel(const int* __restrict__ batch) {
    const int n0 = blockIdx.x * 128;
    const int nend = min(n0 + 128, NN);
    const int tid = threadIdx.x;
    const int c = tid & 63;
    const int which = tid >> 6;     // 0 -> Sh (h), 1 -> Sm (m2)

    float local = 0.f;
    float cntloc = 0.f;
    int gcur = batch[n0];

    for (int n = n0; n < nend; n++) {
        int g = batch[n];
        if (g != gcur) {
            if (which == 0) red1(&g_Sh[gcur * DH + c], local);
            else            red1(&g_Sm[gcur * DH + c], local);
            if (tid == 0)   red1(&g_cnt[gcur], cntloc);
            local = 0.f; cntloc = 0.f; gcur = g;
        }
        float v = (which == 0) ? __half2float(g_hh[(size_t)n * DH + c])
                               : __half2float(g_m2h[(size_t)n * DH + c]);
        local += v;
        cntloc += 1.f;
    }
    if (which == 0) red1(&g_Sh[gcur * DH + c], local);
    else            red1(&g_Sm[gcur * DH + c], local);
    if (tid == 0)   red1(&g_cnt[gcur], cntloc);
}

// out[g] = (Sm[g] @ W2_l + Sh[g] @ W2_r) / cnt[g] + b2
__global__ __launch_bounds__(128) void final_kernel(
    const float* __restrict__ W2l, const float* __restrict__ W2r,
    const float* __restrict__ b2, float* __restrict__ out)
{
    __shared__ float sm[DH], sh[DH];
    int g = blockIdx.x;
    int tid = threadIdx.x;
    if (tid < DH) {
        sm[tid] = g_Sm[g * DH + tid];
        sh[tid] = g_Sh[g * DH + tid];
    }
    __syncthreads();
    float a = 0.f;
#pragma unroll
    for (int k = 0; k < DH; k++) {
        a = fmaf(sm[k], W2l[(size_t)k * 128 + tid], a);
        a = fmaf(sh[k], W2r[(size_t)k * 128 + tid], a);
    }
    out[(size_t)g * 128 + tid] = a / fmaxf(g_cnt[g], 1.0f) + b2[tid];
}

// ---------------- cleanup: restore zero-invariant for the NEXT call ------------
__global__ void cleanup_kernel() {
    int i = blockIdx.x * blockDim.x + threadIdx.x;
    if (i < NN)      g_degn[i] = 0;
    if (i < NG * DH) { g_Sm[i] = 0.f; g_Sh[i] = 0.f; }
    if (i < NG)      g_cnt[i] = 0.f;
    if (i == 0)      g_total = 0;
}

// ---------------- launch ------------------------------------------------------
// ncu profiles launch index 3 -> gemm1_kernel (verify tensor engagement + LDSM).
extern "C" void kernel_launch(void* const* d_in, const int* in_sizes, int n_in,
                              void* d_out, int out_size)
{
    const float* x    = (const float*)d_in[0];
    const float* W1l  = (const float*)d_in[1];
    const float* W1r  = (const float*)d_in[2];
    const float* b1   = (const float*)d_in[3];
    const float* W2l  = (const float*)d_in[4];
    const float* W2r  = (const float*)d_in[5];
    const float* b2   = (const float*)d_in[6];
    const int*   eidx = (const int*)d_in[7];
    const int*   batch= (const int*)d_in[8];
    float* out = (float*)d_out;

    const int* es = eidx;         // edge_index[0] (src)
    const int* ed = eidx + NE;    // edge_index[1] (dst)

    hist_kernel<<<EDGE_BLOCKS, 256>>>(ed);                       // 0
    scan_kernel<<<NB, 256>>>();                                  // 1
    fill_kernel<<<EDGE_BLOCKS, 256>>>(es, ed);                   // 2
    gemm1_kernel<<<GEMM_GRID, 256>>>(x, W1l, W1r, b1);           // 3 <- ncu
    agg1_kernel<<<(NN * 8 + 255) / 256, 256>>>();                // 4
    agg2_kernel<<<(NN * 8 + 255) / 256, 256>>>();                // 5
    pool_kernel<<<(NN + 127) / 128, 128>>>(batch);               // 6
    final_kernel<<<NG, 128>>>(W2l, W2r, b2, out);                // 7
    cleanup_kernel<<<(NN + 255) / 256, 256>>>();                 // 8
}